// round 8
// baseline (speedup 1.0000x reference)
#include <cuda_runtime.h>
#include <math.h>

// iDDPMPrecond: (c_skip=1, c_out=-s, c_in=1/sqrt(s^2+1), c_noise=M-1-argmin_j|s-u_j|)
//
// Closed form: recurrence telescopes to 1+u[j]^2 = A/alpha_bar(j), A=alpha_bar(M),
// alpha_bar(j)=sin^2(c*j), c=pi/(2*M*(1+C2)). Invert analytically:
//   j_real = asin(sqrtA * rsqrt(1+s^2)) / c   (reuses c_in); index error ~0.005.
// Exact argmin verified over the +/-1 window against the REAL u table
// (3 independent cached loads; strict < keeps first index on ties).
// Output region pointers pre-offset on the host (no per-thread address chains).
//
// Converged configuration: every structurally different body (smem binary
// search, 5/3/2-probe analytic, ILP-4, poly-atan) measures 6.6-6.9us harness;
// the kernel is launch-overhead bound (DRAM 0.7%, all pipes <2%). This variant
// holds the best measured harness (6.62us) and ncu (4.93us) times.

__global__ __launch_bounds__(256)
void precond_kernel(const float* __restrict__ sigma,
                    const float* __restrict__ u,
                    float* __restrict__ out_base,      // c_skip region
                    float* __restrict__ o_out,         // c_out
                    float* __restrict__ o_in,          // c_in
                    float* __restrict__ o_noise,       // c_noise
                    int B, int M, int skip_count,
                    float sqrtA, float inv_c)
{
    int tid = blockIdx.x * blockDim.x + threadIdx.x;

    if (tid < skip_count) out_base[tid] = 1.0f;
    if (tid >= B) return;

    float s  = sigma[tid];
    float ci = rsqrtf(fmaf(s, s, 1.0f));     // c_in

    // Analytic candidate index first so probe loads issue ASAP.
    float jf = asinf(sqrtA * ci) * inv_c;
    int jc = __float2int_rn(jf);
    jc = max(1, min(M - 1, jc));

    float u0 = __ldg(&u[jc - 1]);
    float u1 = __ldg(&u[jc]);
    float u2 = __ldg(&u[jc + 1]);

    o_out[tid] = -s;
    o_in[tid]  = ci;

    float d0 = fabsf(s - u0);
    float d1 = fabsf(s - u1);
    float d2 = fabsf(s - u2);

    int   best_j = jc - 1;
    float best_d = d0;
    if (d1 < best_d) { best_d = d1; best_j = jc; }
    if (d2 < best_d) {              best_j = jc + 1; }

    o_noise[tid] = (float)(M - 1 - best_j);
}

extern "C" void kernel_launch(void* const* d_in, const int* in_sizes, int n_in,
                              void* d_out, int out_size)
{
    // inputs per metadata order: x (unused), sigma, u, M
    const float* sigma = (const float*)d_in[1];
    const float* u     = (const float*)d_in[2];
    const int B  = in_sizes[1];
    const int nU = in_sizes[2];
    const int M  = nU - 1;

    // Flattened tuple layout: [c_skip (skip elems)] [c_out B] [c_in B] [c_noise B]
    int skip = out_size - 3 * B;
    if (skip < 0) skip = 0;

    float* ob = (float*)d_out;

    const double PI = 3.14159265358979323846;
    const double C2 = 0.008;
    const double c  = PI * 0.5 / ((double)M * (1.0 + C2));
    const float  sqrtA = (float)sin(c * (double)M);   // sqrt(alpha_bar(M))
    const float  inv_c = (float)(1.0 / c);

    const int threads = 256;
    const int blocks  = (B + threads - 1) / threads;
    precond_kernel<<<blocks, threads>>>(sigma, u,
                                        ob,                 // c_skip
                                        ob + skip,          // c_out
                                        ob + skip + B,      // c_in
                                        ob + skip + 2 * B,  // c_noise
                                        B, M, skip, sqrtA, inv_c);
}

// round 9
// speedup vs baseline: 1.0435x; 1.0435x over previous
#include <cuda_runtime.h>
#include <math.h>

// iDDPMPrecond: (c_skip=1, c_out=-s, c_in=1/sqrt(s^2+1), c_noise=M-1-argmin_j|s-u_j|)
//
// Closed form: recurrence telescopes to 1+u[j]^2 = A/alpha_bar(j), A=alpha_bar(M),
// alpha_bar(j)=sin^2(c*j), c=pi/(2*M*(1+C2)). Invert analytically:
//   j_real = asin(sqrtA * rsqrt(1+s^2)) / c   (reuses c_in); index error ~0.005.
// Exact argmin over the +/-1 window, probed from SHARED memory: the u table
// (4KB) is staged into smem during the prologue, with its fill loads issuing
// concurrently with the sigma load. This removes the second serial global-
// memory latency (probe ~234cyc L2 -> 29cyc LDS) from every thread's chain.
// Strict < keeps first index on ties (matches jnp.argmin).

__global__ __launch_bounds__(256)
void precond_kernel(const float* __restrict__ sigma,
                    const float* __restrict__ u,
                    float* __restrict__ out_base,      // c_skip region
                    float* __restrict__ o_out,         // c_out
                    float* __restrict__ o_in,          // c_in
                    float* __restrict__ o_noise,       // c_noise
                    int B, int M, int skip_count,
                    float sqrtA, float inv_c)
{
    extern __shared__ float su[];          // M+1 floats (4004 B)
    const int nU  = M + 1;
    const int tid = blockIdx.x * blockDim.x + threadIdx.x;

    // Issue the sigma load FIRST so it overlaps the table fill.
    float s = (tid < B) ? sigma[tid] : 0.0f;

    // Table fill: 4 independent iterations (MLP=4), concurrent with sigma load.
    #pragma unroll 4
    for (int i = threadIdx.x; i < nU; i += 256) su[i] = u[i];

    if (tid < skip_count) out_base[tid] = 1.0f;
    __syncthreads();

    if (tid >= B) return;

    float ci = rsqrtf(fmaf(s, s, 1.0f));     // c_in

    // Analytic candidate index.
    float jf = asinf(sqrtA * ci) * inv_c;
    int jc = __float2int_rn(jf);
    jc = max(1, min(M - 1, jc));

    // Exact argmin over [jc-1, jc+1]; 29-cycle smem probes.
    float d0 = fabsf(s - su[jc - 1]);
    float d1 = fabsf(s - su[jc]);
    float d2 = fabsf(s - su[jc + 1]);

    o_out[tid] = -s;
    o_in[tid]  = ci;

    int   best_j = jc - 1;
    float best_d = d0;
    if (d1 < best_d) { best_d = d1; best_j = jc; }
    if (d2 < best_d) {              best_j = jc + 1; }

    o_noise[tid] = (float)(M - 1 - best_j);
}

extern "C" void kernel_launch(void* const* d_in, const int* in_sizes, int n_in,
                              void* d_out, int out_size)
{
    // inputs per metadata order: x (unused), sigma, u, M
    const float* sigma = (const float*)d_in[1];
    const float* u     = (const float*)d_in[2];
    const int B  = in_sizes[1];
    const int nU = in_sizes[2];
    const int M  = nU - 1;

    // Flattened tuple layout: [c_skip (skip elems)] [c_out B] [c_in B] [c_noise B]
    int skip = out_size - 3 * B;
    if (skip < 0) skip = 0;

    float* ob = (float*)d_out;

    const double PI = 3.14159265358979323846;
    const double C2 = 0.008;
    const double c  = PI * 0.5 / ((double)M * (1.0 + C2));
    const float  sqrtA = (float)sin(c * (double)M);   // sqrt(alpha_bar(M))
    const float  inv_c = (float)(1.0 / c);

    const int threads = 256;
    const int blocks  = (B + threads - 1) / threads;
    precond_kernel<<<blocks, threads, nU * sizeof(float)>>>(
        sigma, u,
        ob,                 // c_skip
        ob + skip,          // c_out
        ob + skip + B,      // c_in
        ob + skip + 2 * B,  // c_noise
        B, M, skip, sqrtA, inv_c);
}